// round 8
// baseline (speedup 1.0000x reference)
#include <cuda_runtime.h>
#include <cstdint>

// ---------------------------------------------------------------------------
// Problem constants
// ---------------------------------------------------------------------------
#define B_BATCH 16
#define MEL     2048
#define SRC     512
#define DM      256

#define OUT_ELEMS  (B_BATCH * SRC * DM)    // 2,097,152
#define ATTN_ELEMS (B_BATCH * SRC * MEL)   // 16,777,216

// ---------------------------------------------------------------------------
// Scratch (static __device__ arrays: allocation-free per harness rules)
// ---------------------------------------------------------------------------
__device__ float g_q [B_BATCH * SRC * DM];     //  8 MB : Q  [B,T,D]
__device__ float g_k [B_BATCH * MEL * DM];     // 32 MB : K  [B,S,D]
__device__ float g_vt[B_BATCH * DM  * MEL];    // 32 MB : Vt [B,D,S]
__device__ float g_o [B_BATCH * SRC * DM];     //  8 MB : pre-LN output
__device__ float g_attn_fallback[ATTN_ELEMS];  // 64 MB : only if d_out lacks attn
__device__ unsigned char g_melmask[B_BATCH * MEL];
__device__ unsigned char g_srcmask[B_BATCH * SRC];

// ---------------------------------------------------------------------------
// Mask preparation: detect mask dtype (bool/u8, int32, or float32) from byte
// patterns, then normalize into u8 scratch. All probe reads are in-bounds for
// every candidate dtype (we only read N bytes for probing; wide reads happen
// only after the dtype is proven).
// ---------------------------------------------------------------------------
__global__ void prep_masks_kernel(const void* __restrict__ melraw,
                                  const void* __restrict__ srcraw,
                                  unsigned char* __restrict__ melm,
                                  unsigned char* __restrict__ srcm) {
    __shared__ int fl[4];  // [0]=mel high-byte, [1]=mel odd-pos, [2]=src high, [3]=src odd
    const int tid = threadIdx.x;
    if (tid < 4) fl[tid] = 0;
    __syncthreads();

    const unsigned char* mb = (const unsigned char*)melraw;
    const unsigned char* sb = (const unsigned char*)srcraw;
    int mh = 0, mo = 0, sh = 0, so = 0;
    for (int i = tid; i < 4096; i += 256) {           // <= N bytes for every dtype
        unsigned char c = mb[i];
        if (c >= 2) mh = 1;
        if ((i & 3) && c) mo = 1;
    }
    for (int i = tid; i < 2048; i += 256) {
        unsigned char c = sb[i];
        if (c >= 2) sh = 1;
        if ((i & 3) && c) so = 1;
    }
    if (mh) atomicOr(&fl[0], 1);
    if (mo) atomicOr(&fl[1], 1);
    if (sh) atomicOr(&fl[2], 1);
    if (so) atomicOr(&fl[3], 1);
    __syncthreads();

    // high bytes (0x80/0x3F) => float32; nonzero at non-word-aligned pos => u8; else int32
    const int mmode = fl[0] ? 2 : (fl[1] ? 1 : 0);
    const int smode = fl[2] ? 2 : (fl[3] ? 1 : 0);

    for (int i = tid; i < B_BATCH * MEL; i += 256) {
        bool v = (mmode == 2) ? (((const float*)melraw)[i] != 0.0f)
               : (mmode == 1) ? (mb[i] != 0)
                              : (((const int*)melraw)[i] != 0);
        melm[i] = v ? 1 : 0;
    }
    for (int i = tid; i < B_BATCH * SRC; i += 256) {
        bool v = (smode == 2) ? (((const float*)srcraw)[i] != 0.0f)
               : (smode == 1) ? (sb[i] != 0)
                              : (((const int*)srcraw)[i] != 0);
        srcm[i] = v ? 1 : 0;
    }
}

// ---------------------------------------------------------------------------
// TF32 tensor-core GEMM:  C[M,N] = A[M,K] * B[N,K]^T   (A,B K-major, C N-major)
// CTA tile 128x128, K-chunk 32, 8 warps (2x4) each 64x32 via m16n8k8 mma.
// EPI=0: plain store.  EPI=1: logits (scale + mel-mask column fill with -inf).
// ---------------------------------------------------------------------------
#define TM 128
#define TN 128
#define TK 32
#define SPAD 36   // bank = (4*row + col) % 32  -> conflict-free fragment LDS

__device__ __forceinline__ uint32_t f2tf32(float x) {
    uint32_t u;
    asm("cvt.rna.tf32.f32 %0, %1;" : "=r"(u) : "f"(x));
    return u;
}

template <int EPI>
__global__ __launch_bounds__(256)
void gemm_tt_kernel(const float* __restrict__ A, const float* __restrict__ Bm,
                    float* __restrict__ C, int K, int N,
                    long sA_, long sB_, long sC_,
                    const unsigned char* __restrict__ cmask, int cmask_stride,
                    float scale) {
    __shared__ float shA[TM][SPAD];
    __shared__ float shB[TN][SPAD];

    const int b = blockIdx.z;
    const float* Ab = A  + (long)b * sA_;
    const float* Bb = Bm + (long)b * sB_;
    float*       Cb = C  + (long)b * sC_;

    const int ctaM = blockIdx.y * TM;
    const int ctaN = blockIdx.x * TN;

    const int tid  = threadIdx.x;
    const int warp = tid >> 5, lane = tid & 31;
    const int wr = warp >> 2;        // 0..1  (64-row strip)
    const int wc = warp & 3;         // 0..3  (32-col strip)
    const int g  = lane >> 2;        // octet row
    const int t  = lane & 3;         // quad col

    float acc[4][4][4];
#pragma unroll
    for (int i = 0; i < 4; i++)
#pragma unroll
        for (int j = 0; j < 4; j++)
#pragma unroll
            for (int r = 0; r < 4; r++) acc[i][j][r] = 0.0f;

    for (int k0 = 0; k0 < K; k0 += TK) {
        __syncthreads();
        // Fill A and B tiles (128 rows x 32 cols each), converting to TF32.
#pragma unroll
        for (int i = 0; i < 4; i++) {
            const int f  = i * 256 + tid;
            const int r  = f >> 3;
            const int c4 = (f & 7) << 2;
            float4 va = *reinterpret_cast<const float4*>(Ab + (long)(ctaM + r) * K + (k0 + c4));
            shA[r][c4 + 0] = __uint_as_float(f2tf32(va.x));
            shA[r][c4 + 1] = __uint_as_float(f2tf32(va.y));
            shA[r][c4 + 2] = __uint_as_float(f2tf32(va.z));
            shA[r][c4 + 3] = __uint_as_float(f2tf32(va.w));
            float4 vb = *reinterpret_cast<const float4*>(Bb + (long)(ctaN + r) * K + (k0 + c4));
            shB[r][c4 + 0] = __uint_as_float(f2tf32(vb.x));
            shB[r][c4 + 1] = __uint_as_float(f2tf32(vb.y));
            shB[r][c4 + 2] = __uint_as_float(f2tf32(vb.z));
            shB[r][c4 + 3] = __uint_as_float(f2tf32(vb.w));
        }
        __syncthreads();

#pragma unroll
        for (int kk = 0; kk < 4; kk++) {
            const int kb = kk * 8;
            uint32_t af[4][4];
#pragma unroll
            for (int mt = 0; mt < 4; mt++) {
                const int r = wr * 64 + mt * 16 + g;
                af[mt][0] = __float_as_uint(shA[r    ][kb + t    ]);
                af[mt][1] = __float_as_uint(shA[r + 8][kb + t    ]);
                af[mt][2] = __float_as_uint(shA[r    ][kb + t + 4]);
                af[mt][3] = __float_as_uint(shA[r + 8][kb + t + 4]);
            }
            uint32_t bf[4][2];
#pragma unroll
            for (int nt = 0; nt < 4; nt++) {
                const int n = wc * 32 + nt * 8 + g;
                bf[nt][0] = __float_as_uint(shB[n][kb + t    ]);
                bf[nt][1] = __float_as_uint(shB[n][kb + t + 4]);
            }
#pragma unroll
            for (int mt = 0; mt < 4; mt++)
#pragma unroll
                for (int nt = 0; nt < 4; nt++) {
                    asm volatile(
                        "mma.sync.aligned.m16n8k8.row.col.f32.tf32.tf32.f32 "
                        "{%0,%1,%2,%3}, {%4,%5,%6,%7}, {%8,%9}, {%0,%1,%2,%3};\n"
                        : "+f"(acc[mt][nt][0]), "+f"(acc[mt][nt][1]),
                          "+f"(acc[mt][nt][2]), "+f"(acc[mt][nt][3])
                        : "r"(af[mt][0]), "r"(af[mt][1]), "r"(af[mt][2]), "r"(af[mt][3]),
                          "r"(bf[nt][0]), "r"(bf[nt][1]));
                }
        }
    }

    // Epilogue
    const unsigned char* cm = (EPI == 1) ? (cmask + (long)b * cmask_stride) : nullptr;
    const float NEG = __int_as_float(0xff800000);  // -inf
#pragma unroll
    for (int nt = 0; nt < 4; nt++) {
        const int c0 = ctaN + wc * 32 + nt * 8 + 2 * t;
        bool m0 = false, m1 = false;
        if (EPI == 1) { m0 = cm[c0] != 0; m1 = cm[c0 + 1] != 0; }
#pragma unroll
        for (int mt = 0; mt < 4; mt++) {
            const int r0 = ctaM + wr * 64 + mt * 16 + g;
            float2 v0, v1;
            v0.x = acc[mt][nt][0]; v0.y = acc[mt][nt][1];
            v1.x = acc[mt][nt][2]; v1.y = acc[mt][nt][3];
            if (EPI == 1) {
                v0.x = m0 ? NEG : v0.x * scale;
                v0.y = m1 ? NEG : v0.y * scale;
                v1.x = m0 ? NEG : v1.x * scale;
                v1.y = m1 ? NEG : v1.y * scale;
            }
            *reinterpret_cast<float2*>(Cb + (long)r0 * N + c0)       = v0;
            *reinterpret_cast<float2*>(Cb + (long)(r0 + 8) * N + c0) = v1;
        }
    }
}

// ---------------------------------------------------------------------------
// In-place row softmax over S=2048 (masked mel cols are -inf -> prob 0).
// Rows with src_mask are written as all-zero (post-softmax zeroing).
// One CTA (256 threads) per row; 2 float4 per thread.
// ---------------------------------------------------------------------------
__global__ __launch_bounds__(256)
void softmax_kernel(float* __restrict__ attn, const unsigned char* __restrict__ srcm) {
    const int row = blockIdx.x;
    float4* p = reinterpret_cast<float4*>(attn) + (long)row * (MEL / 4);
    const int tid = threadIdx.x;

    if (srcm[row]) {
        const float4 z = make_float4(0.f, 0.f, 0.f, 0.f);
        p[tid] = z;
        p[tid + 256] = z;
        return;
    }

    float4 v0 = p[tid], v1 = p[tid + 256];
    float m = fmaxf(fmaxf(fmaxf(v0.x, v0.y), fmaxf(v0.z, v0.w)),
                    fmaxf(fmaxf(v1.x, v1.y), fmaxf(v1.z, v1.w)));
    __shared__ float rmax[8], rsum[8];
#pragma unroll
    for (int o = 16; o > 0; o >>= 1) m = fmaxf(m, __shfl_xor_sync(0xffffffffu, m, o));
    if ((tid & 31) == 0) rmax[tid >> 5] = m;
    __syncthreads();
    m = rmax[0];
#pragma unroll
    for (int i = 1; i < 8; i++) m = fmaxf(m, rmax[i]);

    float e[8];
    e[0] = __expf(v0.x - m); e[1] = __expf(v0.y - m);
    e[2] = __expf(v0.z - m); e[3] = __expf(v0.w - m);
    e[4] = __expf(v1.x - m); e[5] = __expf(v1.y - m);
    e[6] = __expf(v1.z - m); e[7] = __expf(v1.w - m);
    float s = ((e[0] + e[1]) + (e[2] + e[3])) + ((e[4] + e[5]) + (e[6] + e[7]));
#pragma unroll
    for (int o = 16; o > 0; o >>= 1) s += __shfl_xor_sync(0xffffffffu, s, o);
    if ((tid & 31) == 0) rsum[tid >> 5] = s;
    __syncthreads();
    s = 0.f;
#pragma unroll
    for (int i = 0; i < 8; i++) s += rsum[i];

    const float inv = 1.0f / s;
    p[tid]       = make_float4(e[0] * inv, e[1] * inv, e[2] * inv, e[3] * inv);
    p[tid + 256] = make_float4(e[4] * inv, e[5] * inv, e[6] * inv, e[7] * inv);
}

// ---------------------------------------------------------------------------
// LayerNorm over D=256. One CTA (256 threads) per row.
// ---------------------------------------------------------------------------
__global__ __launch_bounds__(256)
void ln_kernel(const float* __restrict__ x, const float* __restrict__ gamma,
               const float* __restrict__ beta, float* __restrict__ out) {
    const int row = blockIdx.x;
    const int tid = threadIdx.x;
    const float v = x[(long)row * DM + tid];

    __shared__ float red[8];
    float s = v;
#pragma unroll
    for (int o = 16; o > 0; o >>= 1) s += __shfl_xor_sync(0xffffffffu, s, o);
    if ((tid & 31) == 0) red[tid >> 5] = s;
    __syncthreads();
    float mean = 0.f;
#pragma unroll
    for (int i = 0; i < 8; i++) mean += red[i];
    mean *= (1.0f / DM);

    const float d = v - mean;
    float q = d * d;
    __syncthreads();  // protect red[] reuse
#pragma unroll
    for (int o = 16; o > 0; o >>= 1) q += __shfl_xor_sync(0xffffffffu, q, o);
    if ((tid & 31) == 0) red[tid >> 5] = q;
    __syncthreads();
    float var = 0.f;
#pragma unroll
    for (int i = 0; i < 8; i++) var += red[i];
    var *= (1.0f / DM);

    out[(long)row * DM + tid] = d * rsqrtf(var + 1e-5f) * gamma[tid] + beta[tid];
}

// ---------------------------------------------------------------------------
// Launch
// Inputs (metadata order): mel_encoding, text_encoding, mel_mask, src_mask,
//                          Wq, Wk, Wv, gamma, beta
// Output: concat(output [B,T,D], attn [B,T,S]) as float32.
// ---------------------------------------------------------------------------
extern "C" void kernel_launch(void* const* d_in, const int* in_sizes, int n_in,
                              void* d_out, int out_size) {
    (void)in_sizes; (void)n_in;
    const float* mel     = (const float*)d_in[0];
    const float* text    = (const float*)d_in[1];
    const void*  melraw  = d_in[2];
    const void*  srcraw  = d_in[3];
    const float* Wq      = (const float*)d_in[4];
    const float* Wk      = (const float*)d_in[5];
    const float* Wv      = (const float*)d_in[6];
    const float* gamma   = (const float*)d_in[7];
    const float* beta    = (const float*)d_in[8];

    float* qp;  float* kp;  float* vtp;  float* op;  float* attn_fb;
    unsigned char* mm;  unsigned char* sm;
    cudaGetSymbolAddress((void**)&qp,  g_q);
    cudaGetSymbolAddress((void**)&kp,  g_k);
    cudaGetSymbolAddress((void**)&vtp, g_vt);
    cudaGetSymbolAddress((void**)&op,  g_o);
    cudaGetSymbolAddress((void**)&attn_fb, g_attn_fallback);
    cudaGetSymbolAddress((void**)&mm,  g_melmask);
    cudaGetSymbolAddress((void**)&sm,  g_srcmask);

    // Where do the two outputs live? Default: tuple order, concatenated.
    float* outDst;
    float* attnDst;
    float* base = (float*)d_out;
    if (out_size >= OUT_ELEMS + ATTN_ELEMS) {
        outDst = base;  attnDst = base + OUT_ELEMS;
    } else if (out_size == ATTN_ELEMS) {      // attn only
        outDst = op;    attnDst = base;
    } else {                                   // output only
        outDst = base;  attnDst = attn_fb;
    }

    prep_masks_kernel<<<1, 256>>>(melraw, srcraw, mm, sm);

    const dim3 blk(256);
    // Q = text @ Wq^T : [B,512,256]
    gemm_tt_kernel<0><<<dim3(DM / TN, SRC / TM, B_BATCH), blk>>>(
        text, Wq, qp, DM, DM, (long)SRC * DM, 0L, (long)SRC * DM, nullptr, 0, 1.f);
    // K = mel @ Wk^T : [B,2048,256]
    gemm_tt_kernel<0><<<dim3(DM / TN, MEL / TM, B_BATCH), blk>>>(
        mel, Wk, kp, DM, DM, (long)MEL * DM, 0L, (long)MEL * DM, nullptr, 0, 1.f);
    // Vt = Wv @ mel^T : [B,256,2048]
    gemm_tt_kernel<0><<<dim3(MEL / TN, DM / TM, B_BATCH), blk>>>(
        Wv, mel, vtp, DM, MEL, 0L, (long)MEL * DM, (long)DM * MEL, nullptr, 0, 1.f);
    // logits = (Q @ K^T) / 16, mel-mask -> -inf, into attn region
    gemm_tt_kernel<1><<<dim3(MEL / TN, SRC / TM, B_BATCH), blk>>>(
        qp, kp, attnDst, DM, MEL, (long)SRC * DM, (long)MEL * DM, (long)SRC * MEL,
        mm, MEL, 0.0625f);
    // softmax rows (in place), zero src-masked rows
    softmax_kernel<<<B_BATCH * SRC, 256>>>(attnDst, sm);
    // out_pre = P @ V = P @ Vt^T : [B,512,256]
    gemm_tt_kernel<0><<<dim3(DM / TN, SRC / TM, B_BATCH), blk>>>(
        attnDst, vtp, op, MEL, DM, (long)SRC * MEL, (long)DM * MEL, (long)SRC * DM,
        nullptr, 0, 1.f);
    // LayerNorm -> final output
    ln_kernel<<<B_BATCH * SRC, 256>>>(op, gamma, beta, outDst);
}

// round 15
// speedup vs baseline: 1.1600x; 1.1600x over previous
#include <cuda_runtime.h>
#include <cstdint>

// ---------------------------------------------------------------------------
// Problem constants
// ---------------------------------------------------------------------------
#define B_BATCH 16
#define MEL     2048
#define SRC     512
#define DM      256

#define OUT_ELEMS  (B_BATCH * SRC * DM)    // 2,097,152
#define ATTN_ELEMS (B_BATCH * SRC * MEL)   // 16,777,216

// ---------------------------------------------------------------------------
// Scratch (static __device__ arrays: allocation-free per harness rules)
// ---------------------------------------------------------------------------
__device__ float g_q [B_BATCH * SRC * DM];     //  8 MB : Q  [B,T,D]
__device__ float g_k [B_BATCH * MEL * DM];     // 32 MB : K  [B,S,D]
__device__ float g_vt[B_BATCH * DM  * MEL];    // 32 MB : Vt [B,D,S]
__device__ float g_o [B_BATCH * SRC * DM];     //  8 MB : pre-LN output
__device__ float g_attn_fallback[ATTN_ELEMS];  // 64 MB : only if d_out lacks attn
__device__ unsigned char g_melmask[B_BATCH * MEL];
__device__ unsigned char g_srcmask[B_BATCH * SRC];

// ---------------------------------------------------------------------------
// Mask preparation (dtype sniff: bool/u8, int32, float32 -> u8 scratch)
// ---------------------------------------------------------------------------
__global__ void prep_masks_kernel(const void* __restrict__ melraw,
                                  const void* __restrict__ srcraw,
                                  unsigned char* __restrict__ melm,
                                  unsigned char* __restrict__ srcm) {
    __shared__ int fl[4];
    const int tid = threadIdx.x;
    if (tid < 4) fl[tid] = 0;
    __syncthreads();

    const unsigned char* mb = (const unsigned char*)melraw;
    const unsigned char* sb = (const unsigned char*)srcraw;
    int mh = 0, mo = 0, sh = 0, so = 0;
    for (int i = tid; i < 4096; i += 256) {
        unsigned char c = mb[i];
        if (c >= 2) mh = 1;
        if ((i & 3) && c) mo = 1;
    }
    for (int i = tid; i < 2048; i += 256) {
        unsigned char c = sb[i];
        if (c >= 2) sh = 1;
        if ((i & 3) && c) so = 1;
    }
    if (mh) atomicOr(&fl[0], 1);
    if (mo) atomicOr(&fl[1], 1);
    if (sh) atomicOr(&fl[2], 1);
    if (so) atomicOr(&fl[3], 1);
    __syncthreads();

    const int mmode = fl[0] ? 2 : (fl[1] ? 1 : 0);
    const int smode = fl[2] ? 2 : (fl[3] ? 1 : 0);

    for (int i = tid; i < B_BATCH * MEL; i += 256) {
        bool v = (mmode == 2) ? (((const float*)melraw)[i] != 0.0f)
               : (mmode == 1) ? (mb[i] != 0)
                              : (((const int*)melraw)[i] != 0);
        melm[i] = v ? 1 : 0;
    }
    for (int i = tid; i < B_BATCH * SRC; i += 256) {
        bool v = (smode == 2) ? (((const float*)srcraw)[i] != 0.0f)
               : (smode == 1) ? (sb[i] != 0)
                              : (((const int*)srcraw)[i] != 0);
        srcm[i] = v ? 1 : 0;
    }
}

// ---------------------------------------------------------------------------
// TF32 tensor-core GEMM:  C[M,N] = A[M,K] * B[N,K]^T   (A,B K-major, C N-major)
// CTA tile (32*MT) x 128, K-chunk 16, 8 warps (2 x 4), warp tile (16*MT) x 32.
// 2-stage cp.async pipeline with STATIC shared memory (<=48KB, no attribute
// opt-in, no dynamic smem). TF32 conversion on the fragment path.
// EPI=0: plain store.  EPI=1: logits (scale + mel-mask column fill with -inf).
// ---------------------------------------------------------------------------
#define TN  128
#define TKC 16
#define SP  20    // row stride (floats). Fragment LDS banks: (20*g + t) mod 32
                  // hits all 32 banks (20g mod 32 distinct for g=0..7, +t 0..3).
                  // 80-byte rows keep 16-byte cp.async alignment (80 = 5*16).

__device__ __forceinline__ uint32_t f2tf32(float x) {
    uint32_t u;
    asm("cvt.rna.tf32.f32 %0, %1;" : "=r"(u) : "f"(x));
    return u;
}

__device__ __forceinline__ uint32_t smem_u32(const void* p) {
    return (uint32_t)__cvta_generic_to_shared(p);
}

__device__ __forceinline__ void cp16(uint32_t dst, const float* src) {
    asm volatile("cp.async.cg.shared.global [%0], [%1], 16;\n" :: "r"(dst), "l"(src));
}

template <int EPI, int MT>            // MT=4 -> TM=128 (40KB smem), MT=2 -> TM=64 (30KB)
__global__ __launch_bounds__(256)
void gemm_tt_kernel(const float* __restrict__ A, const float* __restrict__ Bm,
                    float* __restrict__ C, int K, int N,
                    long sA_, long sB_, long sC_,
                    const unsigned char* __restrict__ cmask, int cmask_stride,
                    float scale) {
    constexpr int TM  = 32 * MT;
    constexpr int ACH = MT / 2;        // A float4 chunks per thread per stage
    __shared__ float shA[2][TM][SP];
    __shared__ float shB[2][TN][SP];

    const int b = blockIdx.z;
    const float* Ab = A  + (long)b * sA_;
    const float* Bb = Bm + (long)b * sB_;
    float*       Cb = C  + (long)b * sC_;

    const int ctaM = blockIdx.y * TM;
    const int ctaN = blockIdx.x * TN;

    const int tid  = threadIdx.x;
    const int warp = tid >> 5, lane = tid & 31;
    const int wr = warp >> 2;        // 0..1
    const int wc = warp & 3;         // 0..3
    const int g  = lane >> 2;        // octet row
    const int t  = lane & 3;         // quad col

    // Per-thread fill coordinates (fixed across stages; only k-offset moves).
    // Stage tile is TM x 16 floats for A (TM*4 float4s) and 128 x 16 for B.
    const float* aSrc[ACH];
    uint32_t     aDst[2][ACH];
    const float* bSrc[2];
    uint32_t     bDst[2][2];
#pragma unroll
    for (int i = 0; i < ACH; i++) {
        const int f  = i * 256 + tid;
        const int r  = f >> 2;            // 0..TM-1
        const int c4 = (f & 3) << 2;      // 0,4,8,12
        aSrc[i] = Ab + (long)(ctaM + r) * K + c4;
        aDst[0][i] = smem_u32(&shA[0][r][c4]);
        aDst[1][i] = smem_u32(&shA[1][r][c4]);
    }
#pragma unroll
    for (int i = 0; i < 2; i++) {
        const int f  = i * 256 + tid;
        const int r  = f >> 2;            // 0..127
        const int c4 = (f & 3) << 2;
        bSrc[i] = Bb + (long)(ctaN + r) * K + c4;
        bDst[0][i] = smem_u32(&shB[0][r][c4]);
        bDst[1][i] = smem_u32(&shB[1][r][c4]);
    }

    float acc[MT][4][4];
#pragma unroll
    for (int i = 0; i < MT; i++)
#pragma unroll
        for (int j = 0; j < 4; j++)
#pragma unroll
            for (int r = 0; r < 4; r++) acc[i][j][r] = 0.0f;

    const int niter = K / TKC;   // >= 16 for every call here

    // Prologue: issue stages 0 and 1.
#pragma unroll
    for (int i = 0; i < ACH; i++) cp16(aDst[0][i], aSrc[i]);
#pragma unroll
    for (int i = 0; i < 2; i++)   cp16(bDst[0][i], bSrc[i]);
    asm volatile("cp.async.commit_group;\n");
#pragma unroll
    for (int i = 0; i < ACH; i++) cp16(aDst[1][i], aSrc[i] + TKC);
#pragma unroll
    for (int i = 0; i < 2; i++)   cp16(bDst[1][i], bSrc[i] + TKC);
    asm volatile("cp.async.commit_group;\n");
    asm volatile("cp.async.wait_group 1;\n");
    __syncthreads();

    for (int it = 0; it < niter; ++it) {
        const int s = it & 1;

#pragma unroll
        for (int kk = 0; kk < 2; kk++) {
            const int kb = kk * 8;
            uint32_t af[MT][4];
#pragma unroll
            for (int mt = 0; mt < MT; mt++) {
                const int r = wr * (MT * 16) + mt * 16 + g;
                af[mt][0] = f2tf32(shA[s][r    ][kb + t    ]);
                af[mt][1] = f2tf32(shA[s][r + 8][kb + t    ]);
                af[mt][2] = f2tf32(shA[s][r    ][kb + t + 4]);
                af[mt][3] = f2tf32(shA[s][r + 8][kb + t + 4]);
            }
            uint32_t bf[4][2];
#pragma unroll
            for (int nt = 0; nt < 4; nt++) {
                const int n = wc * 32 + nt * 8 + g;
                bf[nt][0] = f2tf32(shB[s][n][kb + t    ]);
                bf[nt][1] = f2tf32(shB[s][n][kb + t + 4]);
            }
#pragma unroll
            for (int mt = 0; mt < MT; mt++)
#pragma unroll
                for (int nt = 0; nt < 4; nt++) {
                    asm volatile(
                        "mma.sync.aligned.m16n8k8.row.col.f32.tf32.tf32.f32 "
                        "{%0,%1,%2,%3}, {%4,%5,%6,%7}, {%8,%9}, {%0,%1,%2,%3};\n"
                        : "+f"(acc[mt][nt][0]), "+f"(acc[mt][nt][1]),
                          "+f"(acc[mt][nt][2]), "+f"(acc[mt][nt][3])
                        : "r"(af[mt][0]), "r"(af[mt][1]), "r"(af[mt][2]), "r"(af[mt][3]),
                          "r"(bf[nt][0]), "r"(bf[nt][1]));
                }
        }

        __syncthreads();   // all warps done reading stage s
        if (it + 2 < niter) {
            const int koff = (it + 2) * TKC;
#pragma unroll
            for (int i = 0; i < ACH; i++) cp16(aDst[s][i], aSrc[i] + koff);
#pragma unroll
            for (int i = 0; i < 2; i++)   cp16(bDst[s][i], bSrc[i] + koff);
        }
        asm volatile("cp.async.commit_group;\n");
        asm volatile("cp.async.wait_group 1;\n");
        __syncthreads();   // stage (it+1)&1 now ready for everyone
    }

    // Epilogue
    const unsigned char* cm = (EPI == 1) ? (cmask + (long)b * cmask_stride) : nullptr;
    const float NEG = __int_as_float(0xff800000);  // -inf
#pragma unroll
    for (int nt = 0; nt < 4; nt++) {
        const int c0 = ctaN + wc * 32 + nt * 8 + 2 * t;
        bool m0 = false, m1 = false;
        if (EPI == 1) { m0 = cm[c0] != 0; m1 = cm[c0 + 1] != 0; }
#pragma unroll
        for (int mt = 0; mt < MT; mt++) {
            const int r0 = ctaM + wr * (MT * 16) + mt * 16 + g;
            float2 v0, v1;
            v0.x = acc[mt][nt][0]; v0.y = acc[mt][nt][1];
            v1.x = acc[mt][nt][2]; v1.y = acc[mt][nt][3];
            if (EPI == 1) {
                v0.x = m0 ? NEG : v0.x * scale;
                v0.y = m1 ? NEG : v0.y * scale;
                v1.x = m0 ? NEG : v1.x * scale;
                v1.y = m1 ? NEG : v1.y * scale;
            }
            *reinterpret_cast<float2*>(Cb + (long)r0 * N + c0)       = v0;
            *reinterpret_cast<float2*>(Cb + (long)(r0 + 8) * N + c0) = v1;
        }
    }
}

// ---------------------------------------------------------------------------
// In-place row softmax over S=2048; src-masked rows -> all zero.
// ---------------------------------------------------------------------------
__global__ __launch_bounds__(256)
void softmax_kernel(float* __restrict__ attn, const unsigned char* __restrict__ srcm) {
    const int row = blockIdx.x;
    float4* p = reinterpret_cast<float4*>(attn) + (long)row * (MEL / 4);
    const int tid = threadIdx.x;

    if (srcm[row]) {
        const float4 z = make_float4(0.f, 0.f, 0.f, 0.f);
        p[tid] = z;
        p[tid + 256] = z;
        return;
    }

    float4 v0 = p[tid], v1 = p[tid + 256];
    float m = fmaxf(fmaxf(fmaxf(v0.x, v0.y), fmaxf(v0.z, v0.w)),
                    fmaxf(fmaxf(v1.x, v1.y), fmaxf(v1.z, v1.w)));
    __shared__ float rmax[8], rsum[8];
#pragma unroll
    for (int o = 16; o > 0; o >>= 1) m = fmaxf(m, __shfl_xor_sync(0xffffffffu, m, o));
    if ((tid & 31) == 0) rmax[tid >> 5] = m;
    __syncthreads();
    m = rmax[0];
#pragma unroll
    for (int i = 1; i < 8; i++) m = fmaxf(m, rmax[i]);

    float e[8];
    e[0] = __expf(v0.x - m); e[1] = __expf(v0.y - m);
    e[2] = __expf(v0.z - m); e[3] = __expf(v0.w - m);
    e[4] = __expf(v1.x - m); e[5] = __expf(v1.y - m);
    e[6] = __expf(v1.z - m); e[7] = __expf(v1.w - m);
    float s = ((e[0] + e[1]) + (e[2] + e[3])) + ((e[4] + e[5]) + (e[6] + e[7]));
#pragma unroll
    for (int o = 16; o > 0; o >>= 1) s += __shfl_xor_sync(0xffffffffu, s, o);
    if ((tid & 31) == 0) rsum[tid >> 5] = s;
    __syncthreads();
    s = 0.f;
#pragma unroll
    for (int i = 0; i < 8; i++) s += rsum[i];

    const float inv = 1.0f / s;
    p[tid]       = make_float4(e[0] * inv, e[1] * inv, e[2] * inv, e[3] * inv);
    p[tid + 256] = make_float4(e[4] * inv, e[5] * inv, e[6] * inv, e[7] * inv);
}

// ---------------------------------------------------------------------------
// LayerNorm over D=256.
// ---------------------------------------------------------------------------
__global__ __launch_bounds__(256)
void ln_kernel(const float* __restrict__ x, const float* __restrict__ gamma,
               const float* __restrict__ beta, float* __restrict__ out) {
    const int row = blockIdx.x;
    const int tid = threadIdx.x;
    const float v = x[(long)row * DM + tid];

    __shared__ float red[8];
    float s = v;
#pragma unroll
    for (int o = 16; o > 0; o >>= 1) s += __shfl_xor_sync(0xffffffffu, s, o);
    if ((tid & 31) == 0) red[tid >> 5] = s;
    __syncthreads();
    float mean = 0.f;
#pragma unroll
    for (int i = 0; i < 8; i++) mean += red[i];
    mean *= (1.0f / DM);

    const float d = v - mean;
    float q = d * d;
    __syncthreads();
#pragma unroll
    for (int o = 16; o > 0; o >>= 1) q += __shfl_xor_sync(0xffffffffu, q, o);
    if ((tid & 31) == 0) red[tid >> 5] = q;
    __syncthreads();
    float var = 0.f;
#pragma unroll
    for (int i = 0; i < 8; i++) var += red[i];
    var *= (1.0f / DM);

    out[(long)row * DM + tid] = d * rsqrtf(var + 1e-5f) * gamma[tid] + beta[tid];
}

// ---------------------------------------------------------------------------
// Launch (kernel launches only: no attributes, no dynamic smem, no allocs)
// ---------------------------------------------------------------------------
extern "C" void kernel_launch(void* const* d_in, const int* in_sizes, int n_in,
                              void* d_out, int out_size) {
    (void)in_sizes; (void)n_in;
    const float* mel     = (const float*)d_in[0];
    const float* text    = (const float*)d_in[1];
    const void*  melraw  = d_in[2];
    const void*  srcraw  = d_in[3];
    const float* Wq      = (const float*)d_in[4];
    const float* Wk      = (const float*)d_in[5];
    const float* Wv      = (const float*)d_in[6];
    const float* gamma   = (const float*)d_in[7];
    const float* beta    = (const float*)d_in[8];

    float* qp;  float* kp;  float* vtp;  float* op;  float* attn_fb;
    unsigned char* mm;  unsigned char* sm;
    cudaGetSymbolAddress((void**)&qp,  g_q);
    cudaGetSymbolAddress((void**)&kp,  g_k);
    cudaGetSymbolAddress((void**)&vtp, g_vt);
    cudaGetSymbolAddress((void**)&op,  g_o);
    cudaGetSymbolAddress((void**)&attn_fb, g_attn_fallback);
    cudaGetSymbolAddress((void**)&mm,  g_melmask);
    cudaGetSymbolAddress((void**)&sm,  g_srcmask);

    float* outDst;
    float* attnDst;
    float* base = (float*)d_out;
    if (out_size >= OUT_ELEMS + ATTN_ELEMS) {
        outDst = base;  attnDst = base + OUT_ELEMS;
    } else if (out_size == ATTN_ELEMS) {
        outDst = op;    attnDst = base;
    } else {
        outDst = base;  attnDst = attn_fb;
    }

    prep_masks_kernel<<<1, 256>>>(melraw, srcraw, mm, sm);

    const dim3 blk(256);
    // Q = text @ Wq^T : [B,512,256]  (TM=64 -> 256 CTAs)
    gemm_tt_kernel<0, 2><<<dim3(DM / TN, SRC / 64, B_BATCH), blk>>>(
        text, Wq, qp, DM, DM, (long)SRC * DM, 0L, (long)SRC * DM, nullptr, 0, 1.f);
    // K = mel @ Wk^T : [B,2048,256]
    gemm_tt_kernel<0, 4><<<dim3(DM / TN, MEL / 128, B_BATCH), blk>>>(
        mel, Wk, kp, DM, DM, (long)MEL * DM, 0L, (long)MEL * DM, nullptr, 0, 1.f);
    // Vt = Wv @ mel^T : [B,256,2048]
    gemm_tt_kernel<0, 4><<<dim3(MEL / TN, DM / 128, B_BATCH), blk>>>(
        Wv, mel, vtp, DM, MEL, 0L, (long)MEL * DM, (long)DM * MEL, nullptr, 0, 1.f);
    // logits = (Q @ K^T) / 16, mel-mask -> -inf
    gemm_tt_kernel<1, 4><<<dim3(MEL / TN, SRC / 128, B_BATCH), blk>>>(
        qp, kp, attnDst, DM, MEL, (long)SRC * DM, (long)MEL * DM, (long)SRC * MEL,
        mm, MEL, 0.0625f);
    // softmax rows (in place), zero src-masked rows
    softmax_kernel<<<B_BATCH * SRC, 256>>>(attnDst, sm);
    // out_pre = P @ Vt^T : [B,512,256]  (TM=64 -> 256 CTAs)
    gemm_tt_kernel<0, 2><<<dim3(DM / TN, SRC / 64, B_BATCH), blk>>>(
        attnDst, vtp, op, MEL, DM, (long)SRC * MEL, (long)DM * MEL, (long)SRC * DM,
        nullptr, 0, 1.f);
    // LayerNorm -> final output
    ln_kernel<<<B_BATCH * SRC, 256>>>(op, gamma, beta, outDst);
}